// round 11
// baseline (speedup 1.0000x reference)
#include <cuda_runtime.h>
#include <cuda_bf16.h>
#include <cstdint>

#define Bv 32
#define Tv 128
#define Dv 128
#define Hv 8
#define HDv 16
#define Lv 4
#define Vv 50257
#define NT (Bv*Tv)          // 4096 tokens
#define EPSv 1e-5f
#define Wpad 50304          // 393*128 padded vocab
#define NTI 393             // vocab tiles of 128 in logits kernel

// ---------------- scratch (device globals; no allocation allowed) ----------
__device__ float g_x[NT*Dv];
__device__ float g_q[NT*Dv];
__device__ float g_k[NT*Dv];
__device__ float g_v[NT*Dv];
__device__ float g_o[NT*Dv];
__device__ float g_mlp[NT*4*Dv];
__device__ float g_pm[NT*NTI];
__device__ float g_ps[NT*NTI];
__device__ float g_nll[NT];
__device__ __align__(16) __nv_bfloat16 g_hh[NT*Dv];
__device__ __align__(16) __nv_bfloat16 g_hl[NT*Dv];
__device__ __align__(16) __nv_bfloat16 g_wh[Dv*Wpad];
__device__ __align__(16) __nv_bfloat16 g_wl[Dv*Wpad];

// ---------------- warp-mma helpers (baseline PTX: sm_80+, no 'a' feats) ----
__device__ __forceinline__ uint32_t smem_u32(const void* p) {
    uint32_t a;
    asm("{ .reg .u64 t; cvta.to.shared.u64 t, %1; cvt.u32.u64 %0, t; }" : "=r"(a) : "l"(p));
    return a;
}
__device__ __forceinline__ void ldmA(uint32_t* a, uint32_t addr) {
    asm volatile("ldmatrix.sync.aligned.m8n8.x4.shared.b16 {%0,%1,%2,%3}, [%4];"
        : "=r"(a[0]), "=r"(a[1]), "=r"(a[2]), "=r"(a[3]) : "r"(addr));
}
__device__ __forceinline__ void ldmB(uint32_t* b, uint32_t addr) {
    asm volatile("ldmatrix.sync.aligned.m8n8.x2.trans.shared.b16 {%0,%1}, [%2];"
        : "=r"(b[0]), "=r"(b[1]) : "r"(addr));
}
__device__ __forceinline__ void mma16816(float* c, const uint32_t* a, const uint32_t* b) {
    asm volatile("mma.sync.aligned.m16n8k16.row.col.f32.bf16.bf16.f32 "
        "{%0,%1,%2,%3}, {%4,%5,%6,%7}, {%8,%9}, {%0,%1,%2,%3};"
        : "+f"(c[0]), "+f"(c[1]), "+f"(c[2]), "+f"(c[3])
        : "r"(a[0]), "r"(a[1]), "r"(a[2]), "r"(a[3]), "r"(b[0]), "r"(b[1]));
}

// ---------------- embedding ------------------------------------------------
__global__ void embed_k(const int* __restrict__ idx,
                        const float* __restrict__ tok_emb,
                        const float* __restrict__ pos_emb) {
    int tok = blockIdx.x, d = threadIdx.x;
    int t = tok & (Tv - 1);
    g_x[tok*Dv + d] = tok_emb[(size_t)idx[tok]*Dv + d] + pos_emb[t*Dv + d];
}

// ---------------- in-CTA layernorm of a 16x128 smem tile -------------------
// 8 warps, each normalizes 2 rows. One-pass var = E[x^2]-mu^2.
__device__ __forceinline__ void ln_rows16(float (*as)[128],
        const float* __restrict__ gg, const float* __restrict__ bb, int tid) {
    int w = tid >> 5, lane = tid & 31;
    #pragma unroll
    for (int rr = 0; rr < 2; rr++) {
        int r = w*2 + rr;
        float v0 = as[r][lane], v1 = as[r][lane+32],
              v2 = as[r][lane+64], v3 = as[r][lane+96];
        float s = v0+v1+v2+v3;
        float q = v0*v0 + v1*v1 + v2*v2 + v3*v3;
        #pragma unroll
        for (int o = 16; o; o >>= 1) {
            s += __shfl_xor_sync(0xffffffffu, s, o);
            q += __shfl_xor_sync(0xffffffffu, q, o);
        }
        float mean = s * (1.f/128);
        float var  = q * (1.f/128) - mean*mean;
        float inv  = rsqrtf(var + EPSv);
        as[r][lane]    = (v0-mean)*inv*gg[lane]    + bb[lane];
        as[r][lane+32] = (v1-mean)*inv*gg[lane+32] + bb[lane+32];
        as[r][lane+64] = (v2-mean)*inv*gg[lane+64] + bb[lane+64];
        as[r][lane+96] = (v3-mean)*inv*gg[lane+96] + bb[lane+96];
    }
}

// ---------------- fused LN1 + QKV (16 tokens/CTA, 256 CTAs) ----------------
__global__ void __launch_bounds__(256) qkv_ln_k(const float* __restrict__ x,
        const float* __restrict__ wq, const float* __restrict__ wk,
        const float* __restrict__ wv,
        const float* __restrict__ gg, const float* __restrict__ bb) {
    __shared__ float as[16][128];
    int tid = threadIdx.x;
    int tx = tid & 31, ty = tid >> 5;
    int tok0 = blockIdx.x * 16;
    for (int i = tid; i < 16*128; i += 256)
        as[i >> 7][i & 127] = x[(size_t)(tok0 + (i >> 7))*Dv + (i & 127)];
    __syncthreads();
    ln_rows16(as, gg, bb, tid);
    __syncthreads();

    int off[4];
    #pragma unroll
    for (int k = 0; k < 4; k++)
        off[k] = ((tx >> 4) + 2*k)*Dv*HDv + (tx & 15);
    float aq[4][2], ak[4][2], av_[4][2];
    #pragma unroll
    for (int k = 0; k < 4; k++)
        #pragma unroll
        for (int r = 0; r < 2; r++) { aq[k][r]=0.f; ak[k][r]=0.f; av_[k][r]=0.f; }
    #pragma unroll 4
    for (int d = 0; d < Dv; d++) {
        float wqv[4], wkv[4], wvv[4];
        #pragma unroll
        for (int k = 0; k < 4; k++) {
            wqv[k] = wq[off[k] + d*HDv];
            wkv[k] = wk[off[k] + d*HDv];
            wvv[k] = wv[off[k] + d*HDv];
        }
        #pragma unroll
        for (int r = 0; r < 2; r++) {
            float a = as[ty*2 + r][d];
            #pragma unroll
            for (int k = 0; k < 4; k++) {
                aq[k][r]  = fmaf(a, wqv[k], aq[k][r]);
                ak[k][r]  = fmaf(a, wkv[k], ak[k][r]);
                av_[k][r] = fmaf(a, wvv[k], av_[k][r]);
            }
        }
    }
    #pragma unroll
    for (int k = 0; k < 4; k++)
        #pragma unroll
        for (int r = 0; r < 2; r++) {
            size_t o = (size_t)(tok0 + ty*2 + r)*Dv + tx + 32*k;
            g_q[o] = aq[k][r];
            g_k[o] = ak[k][r];
            g_v[o] = av_[k][r];
        }
}

// ---------------- attention ------------------------------------------------
__global__ void attn_k() {
    int bh = blockIdx.x;
    int b = bh >> 3, hh = bh & 7;
    int t = threadIdx.x;
    __shared__ float ks[Tv][HDv];
    __shared__ float vs[Tv][HDv];
    int base = (b*Tv + t)*Dv + hh*HDv;
    float qr[HDv];
    #pragma unroll
    for (int e = 0; e < HDv; e++) {
        ks[t][e] = g_k[base + e];
        vs[t][e] = g_v[base + e];
        qr[e]    = g_q[base + e];
    }
    __syncthreads();
    const float scale = 0.088388347648318447f;
    float m = -1e30f, sum = 0.f;
    float o[HDv];
    #pragma unroll
    for (int e = 0; e < HDv; e++) o[e] = 0.f;
    for (int s = 0; s <= t; s++) {
        float sc = 0.f;
        #pragma unroll
        for (int e = 0; e < HDv; e++) sc = fmaf(qr[e], ks[s][e], sc);
        sc *= scale;
        float nm = fmaxf(m, sc);
        float corr = __expf(m - nm);
        float p = __expf(sc - nm);
        sum = sum * corr + p;
        #pragma unroll
        for (int e = 0; e < HDv; e++) o[e] = fmaf(o[e], corr, p * vs[s][e]);
        m = nm;
    }
    float inv = 1.f / sum;
    #pragma unroll
    for (int e = 0; e < HDv; e++) g_o[base + e] = o[e] * inv;
}

// ---------------- proj: x += o @ W[128,128] + b (16 tokens/CTA) ------------
__global__ void __launch_bounds__(256) proj_k(const float* __restrict__ W,
        const float* __restrict__ bias, float* __restrict__ x) {
    __shared__ float as[16][128];
    int tid = threadIdx.x;
    int tx = tid & 31, ty = tid >> 5;
    int tok0 = blockIdx.x * 16;
    for (int i = tid; i < 16*128; i += 256)
        as[i >> 7][i & 127] = g_o[(size_t)(tok0 + (i >> 7))*Dv + (i & 127)];
    __syncthreads();
    float acc[4][2];
    #pragma unroll
    for (int k = 0; k < 4; k++) {
        float b = bias[tx + 32*k];
        acc[k][0] = b; acc[k][1] = b;
    }
    #pragma unroll 4
    for (int d = 0; d < Dv; d++) {
        const float* wr = W + (size_t)d*Dv + tx;
        float w0 = wr[0], w1 = wr[32], w2 = wr[64], w3 = wr[96];
        #pragma unroll
        for (int r = 0; r < 2; r++) {
            float a = as[ty*2 + r][d];
            acc[0][r] = fmaf(a, w0, acc[0][r]);
            acc[1][r] = fmaf(a, w1, acc[1][r]);
            acc[2][r] = fmaf(a, w2, acc[2][r]);
            acc[3][r] = fmaf(a, w3, acc[3][r]);
        }
    }
    #pragma unroll
    for (int k = 0; k < 4; k++)
        #pragma unroll
        for (int r = 0; r < 2; r++)
            x[(size_t)(tok0 + ty*2 + r)*Dv + tx + 32*k] += acc[k][r];
}

// ---------------- fused LN2 + MLP-up (16 tok x 256 cols/CTA) ---------------
__global__ void __launch_bounds__(256) mlp1_ln_k(const float* __restrict__ x,
        const float* __restrict__ w1, const float* __restrict__ b1,
        const float* __restrict__ gg, const float* __restrict__ bb) {
    __shared__ float as[16][128];
    int tid = threadIdx.x;
    int tx = tid & 31, ty = tid >> 5;
    int tok0 = blockIdx.y * 16;
    int n0 = blockIdx.x * 256;
    for (int i = tid; i < 16*128; i += 256)
        as[i >> 7][i & 127] = x[(size_t)(tok0 + (i >> 7))*Dv + (i & 127)];
    __syncthreads();
    ln_rows16(as, gg, bb, tid);
    __syncthreads();

    float acc[8][2];
    #pragma unroll
    for (int k = 0; k < 8; k++) {
        float b = b1[n0 + tx + 32*k];
        acc[k][0] = b; acc[k][1] = b;
    }
    #pragma unroll 4
    for (int d = 0; d < Dv; d++) {
        const float* wr = w1 + (size_t)d*(4*Dv) + n0 + tx;
        float wv_[8];
        #pragma unroll
        for (int k = 0; k < 8; k++) wv_[k] = wr[32*k];
        #pragma unroll
        for (int r = 0; r < 2; r++) {
            float a = as[ty*2 + r][d];
            #pragma unroll
            for (int k = 0; k < 8; k++) acc[k][r] = fmaf(a, wv_[k], acc[k][r]);
        }
    }
    #pragma unroll
    for (int k = 0; k < 8; k++)
        #pragma unroll
        for (int r = 0; r < 2; r++)
            g_mlp[(size_t)(tok0 + ty*2 + r)*(4*Dv) + n0 + tx + 32*k] =
                fmaxf(acc[k][r], 0.f);
}

// ---------------- MLP-down: x += mlp @ w2[512,128] + b2 (16 tok/CTA) -------
__global__ void __launch_bounds__(256) mlp2_k(const float* __restrict__ w2,
        const float* __restrict__ b2, float* __restrict__ x) {
    __shared__ float as[16][512];
    int tid = threadIdx.x;
    int tx = tid & 31, ty = tid >> 5;
    int tok0 = blockIdx.x * 16;
    for (int i = tid; i < 16*512; i += 256)
        as[i >> 9][i & 511] = g_mlp[(size_t)(tok0 + (i >> 9))*(4*Dv) + (i & 511)];
    __syncthreads();
    float acc[4][2];
    #pragma unroll
    for (int k = 0; k < 4; k++) {
        float b = b2[tx + 32*k];
        acc[k][0] = b; acc[k][1] = b;
    }
    #pragma unroll 4
    for (int d = 0; d < 4*Dv; d++) {
        const float* wr = w2 + (size_t)d*Dv + tx;
        float w0 = wr[0], w1 = wr[32], w2v = wr[64], w3 = wr[96];
        #pragma unroll
        for (int r = 0; r < 2; r++) {
            float a = as[ty*2 + r][d];
            acc[0][r] = fmaf(a, w0, acc[0][r]);
            acc[1][r] = fmaf(a, w1, acc[1][r]);
            acc[2][r] = fmaf(a, w2v, acc[2][r]);
            acc[3][r] = fmaf(a, w3, acc[3][r]);
        }
    }
    #pragma unroll
    for (int k = 0; k < 4; k++)
        #pragma unroll
        for (int r = 0; r < 2; r++)
            x[(size_t)(tok0 + ty*2 + r)*Dv + tx + 32*k] += acc[k][r];
}

// ---------------- fused final LN + bf16 hi/lo split ------------------------
__global__ void lnsplit_k(const float* __restrict__ in,
        const float* __restrict__ gg, const float* __restrict__ bb) {
    int tok = blockIdx.x, d = threadIdx.x;
    float v = in[tok*Dv + d];
    __shared__ float r1[4], r2[4];
    float s = v;
    #pragma unroll
    for (int o = 16; o; o >>= 1) s += __shfl_xor_sync(0xffffffffu, s, o);
    if ((d & 31) == 0) r1[d >> 5] = s;
    __syncthreads();
    float mean = (r1[0] + r1[1] + r1[2] + r1[3]) * (1.f/Dv);
    float c = v - mean;
    float cs = c * c;
    #pragma unroll
    for (int o = 16; o; o >>= 1) cs += __shfl_xor_sync(0xffffffffu, cs, o);
    if ((d & 31) == 0) r2[d >> 5] = cs;
    __syncthreads();
    float var = (r2[0] + r2[1] + r2[2] + r2[3]) * (1.f/Dv);
    float y = c * rsqrtf(var + EPSv) * gg[d] + bb[d];
    __nv_bfloat16 hi = __float2bfloat16_rn(y);
    g_hh[tok*Dv + d] = hi;
    g_hl[tok*Dv + d] = __float2bfloat16_rn(y - __bfloat162float(hi));
}

// ---------------- weight split (fp32 -> bf16 hi+lo) ------------------------
__global__ void wsplit_k(const float* __restrict__ lm_w) {
    int n = blockIdx.x * 128 + threadIdx.x;   // 0..50303
    int k = blockIdx.y;                       // 0..127
    float v = (n < Vv) ? lm_w[(size_t)k*Vv + n] : 0.f;
    __nv_bfloat16 hi = __float2bfloat16_rn(v);
    g_wh[(size_t)k*Wpad + n] = hi;
    g_wl[(size_t)k*Wpad + n] = __float2bfloat16_rn(v - __bfloat162float(hi));
}

// ---------------- LM head via mma.sync bf16 split, fused softmax -----------
#define LDA 136
#define LDW 136
#define A_HALF (64*LDA)
#define W_HALF (128*LDW)
#define SMEM_LM ((2*64*LDA + 2*128*LDW)*2 + 128*4 + 2*64*4*4)

__global__ void __launch_bounds__(256) logits_mma_k(float* __restrict__ out,
        const float* __restrict__ lm_b) {
    extern __shared__ char smem[];
    __nv_bfloat16* As = (__nv_bfloat16*)smem;
    __nv_bfloat16* Ws = As + 2*64*LDA;
    float* sbias = (float*)(Ws + 2*128*LDW);
    float* red_m = sbias + 128;
    float* red_s = red_m + 256;

    int tid = threadIdx.x;
    int tok0 = blockIdx.y * 64;
    int n0 = blockIdx.x * 128;

    for (int i = tid; i < 64*16; i += 256) {
        int m = i >> 4, j = i & 15;
        size_t src = (size_t)(tok0 + m)*Dv + j*8;
        *(uint4*)(As + m*LDA + j*8)          = *(const uint4*)(g_hh + src);
        *(uint4*)(As + A_HALF + m*LDA + j*8) = *(const uint4*)(g_hl + src);
    }
    for (int i = tid; i < 128*16; i += 256) {
        int k = i >> 4, j = i & 15;
        size_t src = (size_t)k*Wpad + n0 + j*8;
        *(uint4*)(Ws + k*LDW + j*8)          = *(const uint4*)(g_wh + src);
        *(uint4*)(Ws + W_HALF + k*LDW + j*8) = *(const uint4*)(g_wl + src);
    }
    if (tid < 128) sbias[tid] = (n0 + tid < Vv) ? lm_b[n0 + tid] : 0.f;
    __syncthreads();

    int wid = tid >> 5, lane = tid & 31;
    int wm = wid >> 2, wn = wid & 3;
    int mbase = wm*32, nbase = wn*32;

    float acc[2][4][4];
    #pragma unroll
    for (int f = 0; f < 2; f++)
        #pragma unroll
        for (int g = 0; g < 4; g++)
            #pragma unroll
            for (int r = 0; r < 4; r++) acc[f][g][r] = 0.f;

    #pragma unroll
    for (int ks = 0; ks < 8; ks++) {
        int k0 = ks*16;
        uint32_t ah[2][4], al[2][4];
        #pragma unroll
        for (int f = 0; f < 2; f++) {
            const __nv_bfloat16* p =
                As + (mbase + f*16 + (lane & 15))*LDA + k0 + ((lane >> 4) << 3);
            ldmA(ah[f], smem_u32(p));
            ldmA(al[f], smem_u32(p + A_HALF));
        }
        uint32_t bh[4][2], bl[4][2];
        #pragma unroll
        for (int g = 0; g < 4; g++) {
            const __nv_bfloat16* p =
                Ws + (k0 + (lane & 15))*LDW + nbase + g*8;
            ldmB(bh[g], smem_u32(p));
            ldmB(bl[g], smem_u32(p + W_HALF));
        }
        #pragma unroll
        for (int f = 0; f < 2; f++)
            #pragma unroll
            for (int g = 0; g < 4; g++) {
                mma16816(acc[f][g], ah[f], bh[g]);
                mma16816(acc[f][g], ah[f], bl[g]);
                mma16816(acc[f][g], al[f], bh[g]);
            }
    }

    int r_in = lane >> 2, cbase = (lane & 3)*2;
    #pragma unroll
    for (int f = 0; f < 2; f++) {
        #pragma unroll
        for (int half = 0; half < 2; half++) {
            int row = mbase + f*16 + r_in + 8*half;
            int tok = tok0 + row;
            float x[8];
            float lm = -1e30f;
            #pragma unroll
            for (int g = 0; g < 4; g++) {
                int cl = nbase + g*8 + cbase;
                float v0 = acc[f][g][2*half]     + sbias[cl];
                float v1 = acc[f][g][2*half + 1] + sbias[cl + 1];
                int n = n0 + cl;
                if (n < Vv)     out[(size_t)tok*Vv + n]     = v0;
                if (n + 1 < Vv) out[(size_t)tok*Vv + n + 1] = v1;
                if (n >= Vv)     v0 = -1e30f;
                if (n + 1 >= Vv) v1 = -1e30f;
                x[2*g] = v0; x[2*g+1] = v1;
                lm = fmaxf(lm, fmaxf(v0, v1));
            }
            lm = fmaxf(lm, __shfl_xor_sync(0xffffffffu, lm, 1));
            lm = fmaxf(lm, __shfl_xor_sync(0xffffffffu, lm, 2));
            float s = 0.f;
            #pragma unroll
            for (int j = 0; j < 8; j++) s += __expf(x[j] - lm);
            s += __shfl_xor_sync(0xffffffffu, s, 1);
            s += __shfl_xor_sync(0xffffffffu, s, 2);
            if ((lane & 3) == 0) { red_m[row*4 + wn] = lm; red_s[row*4 + wn] = s; }
        }
    }
    __syncthreads();
    if (tid < 64) {
        float m = red_m[tid*4], s = red_s[tid*4];
        #pragma unroll
        for (int j = 1; j < 4; j++) {
            float m2 = red_m[tid*4 + j], s2 = red_s[tid*4 + j];
            float nm = fmaxf(m, m2);
            s = s*__expf(m - nm) + s2*__expf(m2 - nm);
            m = nm;
        }
        g_pm[(size_t)(tok0 + tid)*NTI + blockIdx.x] = m;
        g_ps[(size_t)(tok0 + tid)*NTI + blockIdx.x] = s;
    }
}

// ---------------- per-token NLL from partials ------------------------------
__global__ void loss_token_k(const float* __restrict__ logits,
                             const int* __restrict__ targets) {
    int tok = blockIdx.x;
    int lane = threadIdx.x;                  // 32
    float m = -1e30f, s = 0.f;
    for (int i = lane; i < NTI; i += 32) {
        float m2 = g_pm[(size_t)tok*NTI + i];
        float s2 = g_ps[(size_t)tok*NTI + i];
        float nm = fmaxf(m, m2);
        s = s*__expf(m - nm) + s2*__expf(m2 - nm);
        m = nm;
    }
    #pragma unroll
    for (int o = 16; o; o >>= 1) {
        float m2 = __shfl_xor_sync(0xffffffffu, m, o);
        float s2 = __shfl_xor_sync(0xffffffffu, s, o);
        float nm = fmaxf(m, m2);
        s = s*__expf(m - nm) + s2*__expf(m2 - nm);
        m = nm;
    }
    if (lane == 0) {
        float lse = m + logf(s);
        g_nll[tok] = lse - logits[(size_t)tok*Vv + targets[tok]];
    }
}

__global__ void loss_reduce_k(float* __restrict__ out) {
    int tid = threadIdx.x;                    // 256
    float s = 0.f;
    for (int i = tid; i < NT; i += 256) s += g_nll[i];
    #pragma unroll
    for (int o = 16; o; o >>= 1) s += __shfl_xor_sync(0xffffffffu, s, o);
    __shared__ float r[8];
    if ((tid & 31) == 0) r[tid >> 5] = s;
    __syncthreads();
    if (tid == 0) {
        float t = 0.f;
        #pragma unroll
        for (int i = 0; i < 8; i++) t += r[i];
        out[(size_t)NT * Vv] = t * (1.f / NT);
    }
}

// ---------------- launcher -------------------------------------------------
extern "C" void kernel_launch(void* const* d_in, const int* in_sizes, int n_in,
                              void* d_out, int out_size) {
    const int*   idx     = (const int*)d_in[0];
    const int*   targets = (const int*)d_in[1];
    const float* tok_emb = (const float*)d_in[2];
    const float* pos_emb = (const float*)d_in[3];
    const float* wq      = (const float*)d_in[4];
    const float* wk      = (const float*)d_in[5];
    const float* wv      = (const float*)d_in[6];
    const float* wproj   = (const float*)d_in[7];
    const float* bproj   = (const float*)d_in[8];
    const float* w1      = (const float*)d_in[9];
    const float* b1      = (const float*)d_in[10];
    const float* w2      = (const float*)d_in[11];
    const float* b2      = (const float*)d_in[12];
    const float* ln1_g   = (const float*)d_in[13];
    const float* ln1_b   = (const float*)d_in[14];
    const float* ln2_g   = (const float*)d_in[15];
    const float* ln2_b   = (const float*)d_in[16];
    const float* lnf_g   = (const float*)d_in[17];
    const float* lnf_b   = (const float*)d_in[18];
    const float* lm_w    = (const float*)d_in[19];
    const float* lm_b    = (const float*)d_in[20];
    float* out = (float*)d_out;

    float *px;
    cudaGetSymbolAddress((void**)&px, g_x);

    static int smem_set = 0;
    if (!smem_set) {
        cudaFuncSetAttribute(logits_mma_k,
                             cudaFuncAttributeMaxDynamicSharedMemorySize, SMEM_LM);
        smem_set = 1;
    }

    embed_k<<<NT, Dv>>>(idx, tok_emb, pos_emb);
    wsplit_k<<<dim3(Wpad/128, Dv), 128>>>(lm_w);

    for (int l = 0; l < Lv; l++) {
        qkv_ln_k<<<NT/16, 256>>>(px,
            wq + (size_t)l*Hv*Dv*HDv, wk + (size_t)l*Hv*Dv*HDv,
            wv + (size_t)l*Hv*Dv*HDv, ln1_g + l*Dv, ln1_b + l*Dv);
        attn_k<<<Bv*Hv, Tv>>>();
        proj_k<<<NT/16, 256>>>(wproj + (size_t)l*Dv*Dv, bproj + l*Dv, px);
        mlp1_ln_k<<<dim3(2, NT/16), 256>>>(px,
            w1 + (size_t)l*Dv*4*Dv, b1 + l*4*Dv, ln2_g + l*Dv, ln2_b + l*Dv);
        mlp2_k<<<NT/16, 256>>>(w2 + (size_t)l*4*Dv*Dv, b2 + l*Dv, px);
    }

    lnsplit_k<<<NT, Dv>>>(px, lnf_g, lnf_b);

    logits_mma_k<<<dim3(NTI, NT/64), 256, SMEM_LM>>>(out, lm_b);

    loss_token_k<<<NT, 32>>>(out, targets);
    loss_reduce_k<<<1, 256>>>(out);
}

// round 16
// speedup vs baseline: 1.2767x; 1.2767x over previous
#include <cuda_runtime.h>
#include <cuda_bf16.h>
#include <cstdint>

#define Bv 32
#define Tv 128
#define Dv 128
#define Hv 8
#define HDv 16
#define Lv 4
#define Vv 50257
#define NT (Bv*Tv)          // 4096 tokens
#define EPSv 1e-5f
#define Wpad 50304          // 393*128 padded vocab
#define NTI 393             // vocab tiles of 128 in logits kernel

// ---------------- scratch (device globals; no allocation allowed) ----------
__device__ float g_x[NT*Dv];
__device__ float g_q[NT*Dv];
__device__ float g_k[NT*Dv];
__device__ float g_v[NT*Dv];
__device__ float g_o[NT*Dv];
__device__ float g_mlp[NT*4*Dv];
__device__ float g_pm[NT*NTI];
__device__ float g_ps[NT*NTI];
__device__ float g_nll[NT];
__device__ __align__(16) __nv_bfloat16 g_hh[NT*Dv];
__device__ __align__(16) __nv_bfloat16 g_hl[NT*Dv];
__device__ __align__(16) __nv_bfloat16 g_wh[Dv*Wpad];
__device__ __align__(16) __nv_bfloat16 g_wl[Dv*Wpad];

// ---------------- warp-mma helpers -----------------------------------------
__device__ __forceinline__ uint32_t smem_u32(const void* p) {
    uint32_t a;
    asm("{ .reg .u64 t; cvta.to.shared.u64 t, %1; cvt.u32.u64 %0, t; }" : "=r"(a) : "l"(p));
    return a;
}
__device__ __forceinline__ void ldmA(uint32_t* a, uint32_t addr) {
    asm volatile("ldmatrix.sync.aligned.m8n8.x4.shared.b16 {%0,%1,%2,%3}, [%4];"
        : "=r"(a[0]), "=r"(a[1]), "=r"(a[2]), "=r"(a[3]) : "r"(addr));
}
__device__ __forceinline__ void ldmB(uint32_t* b, uint32_t addr) {
    asm volatile("ldmatrix.sync.aligned.m8n8.x2.trans.shared.b16 {%0,%1}, [%2];"
        : "=r"(b[0]), "=r"(b[1]) : "r"(addr));
}
__device__ __forceinline__ void mma16816(float* c, const uint32_t* a, const uint32_t* b) {
    asm volatile("mma.sync.aligned.m16n8k16.row.col.f32.bf16.bf16.f32 "
        "{%0,%1,%2,%3}, {%4,%5,%6,%7}, {%8,%9}, {%0,%1,%2,%3};"
        : "+f"(c[0]), "+f"(c[1]), "+f"(c[2]), "+f"(c[3])
        : "r"(a[0]), "r"(a[1]), "r"(a[2]), "r"(a[3]), "r"(b[0]), "r"(b[1]));
}

// ---------------- embedding ------------------------------------------------
__global__ void embed_k(const int* __restrict__ idx,
                        const float* __restrict__ tok_emb,
                        const float* __restrict__ pos_emb) {
    int tok = blockIdx.x, d = threadIdx.x;
    int t = tok & (Tv - 1);
    g_x[tok*Dv + d] = tok_emb[(size_t)idx[tok]*Dv + d] + pos_emb[t*Dv + d];
}

// ---------------- in-CTA LN: each of NW warps normalizes 4 rows ------------
template<int NW>
__device__ __forceinline__ void ln_rows4(float (*as)[128],
        const float* __restrict__ gg, const float* __restrict__ bb, int tid) {
    int w = tid >> 5, lane = tid & 31;
    #pragma unroll
    for (int rr = 0; rr < 4; rr++) {
        int r = w*4 + rr;
        float v0 = as[r][lane], v1 = as[r][lane+32],
              v2 = as[r][lane+64], v3 = as[r][lane+96];
        float s = v0+v1+v2+v3;
        float q = v0*v0 + v1*v1 + v2*v2 + v3*v3;
        #pragma unroll
        for (int o = 16; o; o >>= 1) {
            s += __shfl_xor_sync(0xffffffffu, s, o);
            q += __shfl_xor_sync(0xffffffffu, q, o);
        }
        float mean = s * (1.f/128);
        float var  = q * (1.f/128) - mean*mean;
        float inv  = rsqrtf(var + EPSv);
        as[r][lane]    = (v0-mean)*inv*gg[lane]    + bb[lane];
        as[r][lane+32] = (v1-mean)*inv*gg[lane+32] + bb[lane+32];
        as[r][lane+64] = (v2-mean)*inv*gg[lane+64] + bb[lane+64];
        as[r][lane+96] = (v3-mean)*inv*gg[lane+96] + bb[lane+96];
    }
}

// ---------------- fused LN1 + QKV: 16 tok/CTA, 128 thr, 4 rows/thread ------
__global__ void __launch_bounds__(128) qkv_ln_k(const float* __restrict__ x,
        const float* __restrict__ wq, const float* __restrict__ wk,
        const float* __restrict__ wv,
        const float* __restrict__ gg, const float* __restrict__ bb) {
    __shared__ float as[16][128];
    int tid = threadIdx.x;
    int tx = tid & 31, ty = tid >> 5;          // ty 0..3 -> 4 rows each
    int tok0 = blockIdx.x * 16;
    for (int i = tid*4; i < 16*128; i += 128*4)
        *(float4*)&as[i >> 7][i & 127] =
            *(const float4*)&x[(size_t)(tok0 + (i >> 7))*Dv + (i & 127)];
    __syncthreads();
    ln_rows4<4>(as, gg, bb, tid);
    __syncthreads();

    int off[4];
    #pragma unroll
    for (int k = 0; k < 4; k++)
        off[k] = ((tx >> 4) + 2*k)*Dv*HDv + (tx & 15);
    float aq[4][4], ak[4][4], av_[4][4];
    #pragma unroll
    for (int k = 0; k < 4; k++)
        #pragma unroll
        for (int r = 0; r < 4; r++) { aq[k][r]=0.f; ak[k][r]=0.f; av_[k][r]=0.f; }
    #pragma unroll 4
    for (int d = 0; d < Dv; d++) {
        float wqv[4], wkv[4], wvv[4];
        #pragma unroll
        for (int k = 0; k < 4; k++) {
            wqv[k] = wq[off[k] + d*HDv];
            wkv[k] = wk[off[k] + d*HDv];
            wvv[k] = wv[off[k] + d*HDv];
        }
        #pragma unroll
        for (int r = 0; r < 4; r++) {
            float a = as[ty*4 + r][d];
            #pragma unroll
            for (int k = 0; k < 4; k++) {
                aq[k][r]  = fmaf(a, wqv[k], aq[k][r]);
                ak[k][r]  = fmaf(a, wkv[k], ak[k][r]);
                av_[k][r] = fmaf(a, wvv[k], av_[k][r]);
            }
        }
    }
    #pragma unroll
    for (int k = 0; k < 4; k++)
        #pragma unroll
        for (int r = 0; r < 4; r++) {
            size_t o = (size_t)(tok0 + ty*4 + r)*Dv + tx + 32*k;
            g_q[o] = aq[k][r];
            g_k[o] = ak[k][r];
            g_v[o] = av_[k][r];
        }
}

// ---------------- attention: 2-way key split, 256 thr ----------------------
__global__ void __launch_bounds__(256) attn_k() {
    int bh = blockIdx.x;
    int b = bh >> 3, hh = bh & 7;
    int tid = threadIdx.x;
    int t = tid & 127, half = tid >> 7;
    __shared__ float ks[Tv][HDv];
    __shared__ float vs[Tv][HDv];
    __shared__ float pm[256], ps[256], po[256][HDv];
    // cooperative K/V stage
    for (int i = tid; i < Tv*HDv; i += 256) {
        int r = i >> 4, e = i & 15;
        int src = (b*Tv + r)*Dv + hh*HDv + e;
        ks[r][e] = g_k[src];
        vs[r][e] = g_v[src];
    }
    int base = (b*Tv + t)*Dv + hh*HDv;
    float qr[HDv];
    #pragma unroll
    for (int e = 0; e < HDv; e++) qr[e] = g_q[base + e];
    __syncthreads();

    const float scale = 0.088388347648318447f;
    int cnt = t + 1;
    int c0 = (cnt + 1) >> 1;
    int s0 = half ? c0 : 0;
    int s1 = half ? cnt : c0;
    float m = -1e30f, sum = 0.f;
    float o[HDv];
    #pragma unroll
    for (int e = 0; e < HDv; e++) o[e] = 0.f;
    for (int s = s0; s < s1; s++) {
        float sc = 0.f;
        #pragma unroll
        for (int e = 0; e < HDv; e++) sc = fmaf(qr[e], ks[s][e], sc);
        sc *= scale;
        float nm = fmaxf(m, sc);
        float corr = __expf(m - nm);
        float p = __expf(sc - nm);
        sum = sum * corr + p;
        #pragma unroll
        for (int e = 0; e < HDv; e++) o[e] = fmaf(o[e], corr, p * vs[s][e]);
        m = nm;
    }
    pm[tid] = m; ps[tid] = sum;
    #pragma unroll
    for (int e = 0; e < HDv; e++) po[tid][e] = o[e];
    __syncthreads();
    if (tid < 128) {
        float m0 = pm[tid], m1 = pm[tid + 128];
        float M = fmaxf(m0, m1);
        float e0 = __expf(m0 - M), e1 = __expf(m1 - M);
        float S = ps[tid]*e0 + ps[tid + 128]*e1;
        float inv = 1.f / S;
        #pragma unroll
        for (int e = 0; e < HDv; e++)
            g_o[base + e] = (po[tid][e]*e0 + po[tid + 128][e]*e1) * inv;
    }
}

// ---------------- proj: x += o @ W[128,128] + b (16 tok, 128 thr) ----------
__global__ void __launch_bounds__(128) proj_k(const float* __restrict__ W,
        const float* __restrict__ bias, float* __restrict__ x) {
    __shared__ float as[16][128];
    int tid = threadIdx.x;
    int tx = tid & 31, ty = tid >> 5;
    int tok0 = blockIdx.x * 16;
    for (int i = tid*4; i < 16*128; i += 128*4)
        *(float4*)&as[i >> 7][i & 127] =
            *(const float4*)&g_o[(size_t)(tok0 + (i >> 7))*Dv + (i & 127)];
    __syncthreads();
    float acc[4][4];
    #pragma unroll
    for (int k = 0; k < 4; k++) {
        float b = bias[tx + 32*k];
        #pragma unroll
        for (int r = 0; r < 4; r++) acc[k][r] = b;
    }
    #pragma unroll 4
    for (int d = 0; d < Dv; d++) {
        const float* wr = W + (size_t)d*Dv + tx;
        float w0 = wr[0], w1 = wr[32], w2 = wr[64], w3 = wr[96];
        #pragma unroll
        for (int r = 0; r < 4; r++) {
            float a = as[ty*4 + r][d];
            acc[0][r] = fmaf(a, w0, acc[0][r]);
            acc[1][r] = fmaf(a, w1, acc[1][r]);
            acc[2][r] = fmaf(a, w2, acc[2][r]);
            acc[3][r] = fmaf(a, w3, acc[3][r]);
        }
    }
    #pragma unroll
    for (int k = 0; k < 4; k++)
        #pragma unroll
        for (int r = 0; r < 4; r++)
            x[(size_t)(tok0 + ty*4 + r)*Dv + tx + 32*k] += acc[k][r];
}

// ---------------- fused LN2 + MLP-up: 32 tok x 128 cols, 256 thr -----------
__global__ void __launch_bounds__(256) mlp1_ln_k(const float* __restrict__ x,
        const float* __restrict__ w1, const float* __restrict__ b1,
        const float* __restrict__ gg, const float* __restrict__ bb) {
    __shared__ float as[32][128];
    int tid = threadIdx.x;
    int tx = tid & 31, ty = tid >> 5;
    int tok0 = blockIdx.y * 32;
    int n0 = blockIdx.x * 128;
    for (int i = tid*4; i < 32*128; i += 256*4)
        *(float4*)&as[i >> 7][i & 127] =
            *(const float4*)&x[(size_t)(tok0 + (i >> 7))*Dv + (i & 127)];
    __syncthreads();
    ln_rows4<8>(as, gg, bb, tid);
    __syncthreads();

    float acc[4][4];
    #pragma unroll
    for (int k = 0; k < 4; k++) {
        float b = b1[n0 + tx + 32*k];
        #pragma unroll
        for (int r = 0; r < 4; r++) acc[k][r] = b;
    }
    #pragma unroll 4
    for (int d = 0; d < Dv; d++) {
        const float* wr = w1 + (size_t)d*(4*Dv) + n0 + tx;
        float w0 = wr[0], w1v = wr[32], w2 = wr[64], w3 = wr[96];
        #pragma unroll
        for (int r = 0; r < 4; r++) {
            float a = as[ty*4 + r][d];
            acc[0][r] = fmaf(a, w0, acc[0][r]);
            acc[1][r] = fmaf(a, w1v, acc[1][r]);
            acc[2][r] = fmaf(a, w2, acc[2][r]);
            acc[3][r] = fmaf(a, w3, acc[3][r]);
        }
    }
    #pragma unroll
    for (int k = 0; k < 4; k++)
        #pragma unroll
        for (int r = 0; r < 4; r++)
            g_mlp[(size_t)(tok0 + ty*4 + r)*(4*Dv) + n0 + tx + 32*k] =
                fmaxf(acc[k][r], 0.f);
}

// ---------------- MLP-down: x += mlp @ w2[512,128] + b2 (16 tok, 128 thr) --
__global__ void __launch_bounds__(128) mlp2_k(const float* __restrict__ w2,
        const float* __restrict__ b2, float* __restrict__ x) {
    __shared__ float as[16][512];
    int tid = threadIdx.x;
    int tx = tid & 31, ty = tid >> 5;
    int tok0 = blockIdx.x * 16;
    for (int i = tid*4; i < 16*512; i += 128*4)
        *(float4*)&as[i >> 9][i & 511] =
            *(const float4*)&g_mlp[(size_t)(tok0 + (i >> 9))*(4*Dv) + (i & 511)];
    __syncthreads();
    float acc[4][4];
    #pragma unroll
    for (int k = 0; k < 4; k++) {
        float b = b2[tx + 32*k];
        #pragma unroll
        for (int r = 0; r < 4; r++) acc[k][r] = b;
    }
    #pragma unroll 4
    for (int d = 0; d < 4*Dv; d++) {
        const float* wr = w2 + (size_t)d*Dv + tx;
        float w0 = wr[0], w1 = wr[32], w2v = wr[64], w3 = wr[96];
        #pragma unroll
        for (int r = 0; r < 4; r++) {
            float a = as[ty*4 + r][d];
            acc[0][r] = fmaf(a, w0, acc[0][r]);
            acc[1][r] = fmaf(a, w1, acc[1][r]);
            acc[2][r] = fmaf(a, w2v, acc[2][r]);
            acc[3][r] = fmaf(a, w3, acc[3][r]);
        }
    }
    #pragma unroll
    for (int k = 0; k < 4; k++)
        #pragma unroll
        for (int r = 0; r < 4; r++)
            x[(size_t)(tok0 + ty*4 + r)*Dv + tx + 32*k] += acc[k][r];
}

// ---------------- fused final LN + bf16 hi/lo split ------------------------
__global__ void lnsplit_k(const float* __restrict__ in,
        const float* __restrict__ gg, const float* __restrict__ bb) {
    int tok = blockIdx.x, d = threadIdx.x;
    float v = in[tok*Dv + d];
    __shared__ float r1[4], r2[4];
    float s = v;
    #pragma unroll
    for (int o = 16; o; o >>= 1) s += __shfl_xor_sync(0xffffffffu, s, o);
    if ((d & 31) == 0) r1[d >> 5] = s;
    __syncthreads();
    float mean = (r1[0] + r1[1] + r1[2] + r1[3]) * (1.f/Dv);
    float c = v - mean;
    float cs = c * c;
    #pragma unroll
    for (int o = 16; o; o >>= 1) cs += __shfl_xor_sync(0xffffffffu, cs, o);
    if ((d & 31) == 0) r2[d >> 5] = cs;
    __syncthreads();
    float var = (r2[0] + r2[1] + r2[2] + r2[3]) * (1.f/Dv);
    float y = c * rsqrtf(var + EPSv) * gg[d] + bb[d];
    __nv_bfloat16 hi = __float2bfloat16_rn(y);
    g_hh[tok*Dv + d] = hi;
    g_hl[tok*Dv + d] = __float2bfloat16_rn(y - __bfloat162float(hi));
}

// ---------------- weight split (fp32 -> bf16 hi+lo) ------------------------
__global__ void wsplit_k(const float* __restrict__ lm_w) {
    int n = blockIdx.x * 128 + threadIdx.x;
    int k = blockIdx.y;
    float v = (n < Vv) ? lm_w[(size_t)k*Vv + n] : 0.f;
    __nv_bfloat16 hi = __float2bfloat16_rn(v);
    g_wh[(size_t)k*Wpad + n] = hi;
    g_wl[(size_t)k*Wpad + n] = __float2bfloat16_rn(v - __bfloat162float(hi));
}

// ---------------- LM head via mma.sync bf16 split, fused softmax -----------
#define LDA 136
#define LDW 136
#define A_HALF (64*LDA)
#define W_HALF (128*LDW)
#define SMEM_LM ((2*64*LDA + 2*128*LDW)*2 + 128*4 + 2*64*4*4)

__global__ void __launch_bounds__(256) logits_mma_k(float* __restrict__ out,
        const float* __restrict__ lm_b) {
    extern __shared__ char smem[];
    __nv_bfloat16* As = (__nv_bfloat16*)smem;
    __nv_bfloat16* Ws = As + 2*64*LDA;
    float* sbias = (float*)(Ws + 2*128*LDW);
    float* red_m = sbias + 128;
    float* red_s = red_m + 256;

    int tid = threadIdx.x;
    int tok0 = blockIdx.y * 64;
    int n0 = blockIdx.x * 128;

    for (int i = tid; i < 64*16; i += 256) {
        int m = i >> 4, j = i & 15;
        size_t src = (size_t)(tok0 + m)*Dv + j*8;
        *(uint4*)(As + m*LDA + j*8)          = *(const uint4*)(g_hh + src);
        *(uint4*)(As + A_HALF + m*LDA + j*8) = *(const uint4*)(g_hl + src);
    }
    for (int i = tid; i < 128*16; i += 256) {
        int k = i >> 4, j = i & 15;
        size_t src = (size_t)k*Wpad + n0 + j*8;
        *(uint4*)(Ws + k*LDW + j*8)          = *(const uint4*)(g_wh + src);
        *(uint4*)(Ws + W_HALF + k*LDW + j*8) = *(const uint4*)(g_wl + src);
    }
    if (tid < 128) sbias[tid] = (n0 + tid < Vv) ? lm_b[n0 + tid] : 0.f;
    __syncthreads();

    int wid = tid >> 5, lane = tid & 31;
    int wm = wid >> 2, wn = wid & 3;
    int mbase = wm*32, nbase = wn*32;

    float acc[2][4][4];
    #pragma unroll
    for (int f = 0; f < 2; f++)
        #pragma unroll
        for (int g = 0; g < 4; g++)
            #pragma unroll
            for (int r = 0; r < 4; r++) acc[f][g][r] = 0.f;

    #pragma unroll
    for (int ks = 0; ks < 8; ks++) {
        int k0 = ks*16;
        uint32_t ah[2][4], al[2][4];
        #pragma unroll
        for (int f = 0; f < 2; f++) {
            const __nv_bfloat16* p =
                As + (mbase + f*16 + (lane & 15))*LDA + k0 + ((lane >> 4) << 3);
            ldmA(ah[f], smem_u32(p));
            ldmA(al[f], smem_u32(p + A_HALF));
        }
        uint32_t bh[4][2], bl[4][2];
        #pragma unroll
        for (int g = 0; g < 4; g++) {
            const __nv_bfloat16* p =
                Ws + (k0 + (lane & 15))*LDW + nbase + g*8;
            ldmB(bh[g], smem_u32(p));
            ldmB(bl[g], smem_u32(p + W_HALF));
        }
        #pragma unroll
        for (int f = 0; f < 2; f++)
            #pragma unroll
            for (int g = 0; g < 4; g++) {
                mma16816(acc[f][g], ah[f], bh[g]);
                mma16816(acc[f][g], ah[f], bl[g]);
                mma16816(acc[f][g], al[f], bh[g]);
            }
    }

    int r_in = lane >> 2, cbase = (lane & 3)*2;
    #pragma unroll
    for (int f = 0; f < 2; f++) {
        #pragma unroll
        for (int half = 0; half < 2; half++) {
            int row = mbase + f*16 + r_in + 8*half;
            int tok = tok0 + row;
            float x[8];
            float lm = -1e30f;
            #pragma unroll
            for (int g = 0; g < 4; g++) {
                int cl = nbase + g*8 + cbase;
                float v0 = acc[f][g][2*half]     + sbias[cl];
                float v1 = acc[f][g][2*half + 1] + sbias[cl + 1];
                int n = n0 + cl;
                if (n < Vv)     out[(size_t)tok*Vv + n]     = v0;
                if (n + 1 < Vv) out[(size_t)tok*Vv + n + 1] = v1;
                if (n >= Vv)     v0 = -1e30f;
                if (n + 1 >= Vv) v1 = -1e30f;
                x[2*g] = v0; x[2*g+1] = v1;
                lm = fmaxf(lm, fmaxf(v0, v1));
            }
            lm = fmaxf(lm, __shfl_xor_sync(0xffffffffu, lm, 1));
            lm = fmaxf(lm, __shfl_xor_sync(0xffffffffu, lm, 2));
            float s = 0.f;
            #pragma unroll
            for (int j = 0; j < 8; j++) s += __expf(x[j] - lm);
            s += __shfl_xor_sync(0xffffffffu, s, 1);
            s += __shfl_xor_sync(0xffffffffu, s, 2);
            if ((lane & 3) == 0) { red_m[row*4 + wn] = lm; red_s[row*4 + wn] = s; }
        }
    }
    __syncthreads();
    if (tid < 64) {
        float m = red_m[tid*4], s = red_s[tid*4];
        #pragma unroll
        for (int j = 1; j < 4; j++) {
            float m2 = red_m[tid*4 + j], s2 = red_s[tid*4 + j];
            float nm = fmaxf(m, m2);
            s = s*__expf(m - nm) + s2*__expf(m2 - nm);
            m = nm;
        }
        g_pm[(size_t)(tok0 + tid)*NTI + blockIdx.x] = m;
        g_ps[(size_t)(tok0 + tid)*NTI + blockIdx.x] = s;
    }
}

// ---------------- per-token NLL from partials ------------------------------
__global__ void loss_token_k(const float* __restrict__ logits,
                             const int* __restrict__ targets) {
    int tok = blockIdx.x;
    int lane = threadIdx.x;
    float m = -1e30f, s = 0.f;
    for (int i = lane; i < NTI; i += 32) {
        float m2 = g_pm[(size_t)tok*NTI + i];
        float s2 = g_ps[(size_t)tok*NTI + i];
        float nm = fmaxf(m, m2);
        s = s*__expf(m - nm) + s2*__expf(m2 - nm);
        m = nm;
    }
    #pragma unroll
    for (int o = 16; o; o >>= 1) {
        float m2 = __shfl_xor_sync(0xffffffffu, m, o);
        float s2 = __shfl_xor_sync(0xffffffffu, s, o);
        float nm = fmaxf(m, m2);
        s = s*__expf(m - nm) + s2*__expf(m2 - nm);
        m = nm;
    }
    if (lane == 0) {
        float lse = m + logf(s);
        g_nll[tok] = lse - logits[(size_t)tok*Vv + targets[tok]];
    }
}

__global__ void loss_reduce_k(float* __restrict__ out) {
    int tid = threadIdx.x;
    float s = 0.f;
    for (int i = tid; i < NT; i += 256) s += g_nll[i];
    #pragma unroll
    for (int o = 16; o; o >>= 1) s += __shfl_xor_sync(0xffffffffu, s, o);
    __shared__ float r[8];
    if ((tid & 31) == 0) r[tid >> 5] = s;
    __syncthreads();
    if (tid == 0) {
        float t = 0.f;
        #pragma unroll
        for (int i = 0; i < 8; i++) t += r[i];
        out[(size_t)NT * Vv] = t * (1.f / NT);
    }
}

// ---------------- launcher -------------------------------------------------
extern "C" void kernel_launch(void* const* d_in, const int* in_sizes, int n_in,
                              void* d_out, int out_size) {
    const int*   idx     = (const int*)d_in[0];
    const int*   targets = (const int*)d_in[1];
    const float* tok_emb = (const float*)d_in[2];
    const float* pos_emb = (const float*)d_in[3];
    const float* wq      = (const float*)d_in[4];
    const float* wk      = (const float*)d_in[5];
    const float* wv      = (const float*)d_in[6];
    const float* wproj   = (const float*)d_in[7];
    const float* bproj   = (const float*)d_in[8];
    const float* w1      = (const float*)d_in[9];
    const float* b1      = (const float*)d_in[10];
    const float* w2      = (const float*)d_in[11];
    const float* b2      = (const float*)d_in[12];
    const float* ln1_g   = (const float*)d_in[13];
    const float* ln1_b   = (const float*)d_in[14];
    const float* ln2_g   = (const float*)d_in[15];
    const float* ln2_b   = (const float*)d_in[16];
    const float* lnf_g   = (const float*)d_in[17];
    const float* lnf_b   = (const float*)d_in[18];
    const float* lm_w    = (const float*)d_in[19];
    const float* lm_b    = (const float*)d_in[20];
    float* out = (float*)d_out;

    float *px;
    cudaGetSymbolAddress((void**)&px, g_x);

    static int smem_set = 0;
    if (!smem_set) {
        cudaFuncSetAttribute(logits_mma_k,
                             cudaFuncAttributeMaxDynamicSharedMemorySize, SMEM_LM);
        smem_set = 1;
    }

    embed_k<<<NT, Dv>>>(idx, tok_emb, pos_emb);
    wsplit_k<<<dim3(Wpad/128, Dv), 128>>>(lm_w);

    for (int l = 0; l < Lv; l++) {
        qkv_ln_k<<<NT/16, 128>>>(px,
            wq + (size_t)l*Hv*Dv*HDv, wk + (size_t)l*Hv*Dv*HDv,
            wv + (size_t)l*Hv*Dv*HDv, ln1_g + l*Dv, ln1_b + l*Dv);
        attn_k<<<Bv*Hv, 256>>>();
        proj_k<<<NT/16, 128>>>(wproj + (size_t)l*Dv*Dv, bproj + l*Dv, px);
        mlp1_ln_k<<<dim3(4, NT/32), 256>>>(px,
            w1 + (size_t)l*Dv*4*Dv, b1 + l*4*Dv, ln2_g + l*Dv, ln2_b + l*Dv);
        mlp2_k<<<NT/16, 128>>>(w2 + (size_t)l*4*Dv*Dv, b2 + l*Dv, px);
    }

    lnsplit_k<<<NT, Dv>>>(px, lnf_g, lnf_b);

    logits_mma_k<<<dim3(NTI, NT/64), 256, SMEM_LM>>>(out, lm_b);

    loss_token_k<<<NT, 32>>>(out, targets);
    loss_reduce_k<<<1, 256>>>(out);
}